// round 9
// baseline (speedup 1.0000x reference)
#include <cuda_runtime.h>

#define B 32
#define S 2048
#define H 32
#define HKV 8
#define G 4            // H / HKV
#define D 128
#define SPLITS 4
#define CHUNK (S / SPLITS)   // 512
#define NWARP 8
#define SCALE 0.08838834764831845f
#define NEG -1e30f

// split-KV partial scratch (allocation-free: __device__ globals)
__device__ float g_part_o[B * HKV * SPLITS * G * D];
__device__ float g_part_m[B * HKV * SPLITS * G];
__device__ float g_part_l[B * HKV * SPLITS * G];
__device__ int   g_cnt[B * HKV];   // zero-init; every replay returns it to zero

// 11-shuffle 4-head warp reduction: lane L returns the full 32-lane sum of
// head (L & 3)'s partial. sg[g] holds this lane's partial for head g.
__device__ __forceinline__ float reduce4(float sg[G], int lane)
{
    #pragma unroll
    for (int g = 0; g < G; g++) {
        sg[g] += __shfl_xor_sync(0xffffffffu, sg[g], 1);
        sg[g] += __shfl_xor_sync(0xffffffffu, sg[g], 2);
    }
    const int h = lane & 3;
    float v = (h == 0) ? sg[0] : (h == 1) ? sg[1] : (h == 2) ? sg[2] : sg[3];
    v += __shfl_xor_sync(0xffffffffu, v, 4);
    v += __shfl_xor_sync(0xffffffffu, v, 8);
    v += __shfl_xor_sync(0xffffffffu, v, 16);
    return v;
}

__global__ __launch_bounds__(256, 4) void attn_fused_kernel(
    const float* __restrict__ q,
    const float* __restrict__ knew,
    const float* __restrict__ vnew,
    const float* __restrict__ kbuf,
    const float* __restrict__ vbuf,
    const int*   __restrict__ req_to_token,
    const int*   __restrict__ seq_lens,
    const int*   __restrict__ out_cache_loc,
    float*       __restrict__ out)
{
    const int bh    = blockIdx.x;           // b * HKV + kh
    const int b     = bh / HKV;
    const int kh    = bh % HKV;
    const int split = blockIdx.y;
    const int tid   = threadIdx.x;
    const int lane  = tid & 31;
    const int warp  = tid >> 5;

    const int seq_len = seq_lens[b];
    const int s0      = split * CHUNK;
    const int nt      = min(seq_len - s0, CHUNK);
    const int pbase   = (bh * SPLITS + split) * G;

    __shared__ float red[NWARP * G * D];    // per-warp unnormalized acc (16 KB)
    __shared__ float ml2[NWARP][G][2];      // per-warp (m, l)
    __shared__ float wts[NWARP][G];         // merge weights
    __shared__ float m_s[G], l_s[G];
    __shared__ int   is_last;

    if (nt > 0) {
        const int out_loc = out_cache_loc[b];

        // q (scaled) in registers: one float4 per head per lane
        float4 qv[G];
        #pragma unroll
        for (int g = 0; g < G; g++) {
            float4 t = *(const float4*)(q + ((size_t)b * H + kh * G + g) * D + lane * 4);
            qv[g] = make_float4(t.x * SCALE, t.y * SCALE, t.z * SCALE, t.w * SCALE);
        }

        const float* knew_ptr = knew + ((size_t)b * HKV + kh) * D;
        const float* vnew_ptr = vnew + ((size_t)b * HKV + kh) * D;
        const int*   rtab     = req_to_token + (size_t)b * S + s0;

        // ---------- single pass: online softmax, warp-per-token ----------
        float m[G], l[G];
        float4 acc[G];
        #pragma unroll
        for (int g = 0; g < G; g++) {
            m[g] = NEG; l[g] = 0.f;
            acc[g] = make_float4(0.f, 0.f, 0.f, 0.f);
        }

        int t = warp;
        float4 kn, vn;
        if (t < nt) {                       // prime the pipeline (K and V both)
            const int loc = rtab[t];
            const bool isnew = (loc == out_loc);
            const float* kp = isnew ? knew_ptr : (kbuf + ((size_t)loc * HKV + kh) * D);
            const float* vp = isnew ? vnew_ptr : (vbuf + ((size_t)loc * HKV + kh) * D);
            kn = *(const float4*)(kp + lane * 4);
            vn = *(const float4*)(vp + lane * 4);
        }
        for (; t < nt; t += NWARP) {
            const float4 kc = kn, vc = vn;
            const int tn = t + NWARP;
            if (tn < nt) {                  // issue next K+V LDGs before compute
                const int loc = rtab[tn];
                const bool isnew = (loc == out_loc);
                const float* kp = isnew ? knew_ptr : (kbuf + ((size_t)loc * HKV + kh) * D);
                const float* vp = isnew ? vnew_ptr : (vbuf + ((size_t)loc * HKV + kh) * D);
                kn = *(const float4*)(kp + lane * 4);
                vn = *(const float4*)(vp + lane * 4);
            }
            float sg[G];
            #pragma unroll
            for (int g = 0; g < G; g++)
                sg[g] = kc.x * qv[g].x + kc.y * qv[g].y + kc.z * qv[g].z + kc.w * qv[g].w;
            const float r = reduce4(sg, lane);   // lane L: total for head L&3
            float sv[G];
            sv[0] = __shfl_sync(0xffffffffu, r, 0);
            sv[1] = __shfl_sync(0xffffffffu, r, 1);
            sv[2] = __shfl_sync(0xffffffffu, r, 2);
            sv[3] = __shfl_sync(0xffffffffu, r, 3);
            #pragma unroll
            for (int g = 0; g < G; g++) {
                const float mn    = fmaxf(m[g], sv[g]);
                const float scale = __expf(m[g] - mn);   // exp(-inf)=0 on first token
                const float e     = __expf(sv[g] - mn);
                l[g] = l[g] * scale + e;
                acc[g].x = acc[g].x * scale + e * vc.x;
                acc[g].y = acc[g].y * scale + e * vc.y;
                acc[g].z = acc[g].z * scale + e * vc.z;
                acc[g].w = acc[g].w * scale + e * vc.w;
                m[g] = mn;
            }
        }

        // ---------- deterministic cross-warp merge ----------
        #pragma unroll
        for (int g = 0; g < G; g++)
            *(float4*)&red[(warp * G + g) * D + lane * 4] = acc[g];
        if (lane < G) {                     // lane g writes head g's (m, l)
            ml2[warp][lane][0] = m[lane];
            ml2[warp][lane][1] = l[lane];
        }
        __syncthreads();

        if (tid < G) {                      // thread g: merge stats across warps
            const int g = tid;
            float mm = NEG;
            #pragma unroll
            for (int w = 0; w < NWARP; w++) mm = fmaxf(mm, ml2[w][g][0]);
            float L = 0.f;
            #pragma unroll
            for (int w = 0; w < NWARP; w++) {
                const float wt = __expf(ml2[w][g][0] - mm);
                wts[w][g] = wt;
                L += ml2[w][g][1] * wt;
            }
            m_s[g] = mm; l_s[g] = L;
        }
        __syncthreads();

        for (int i = tid; i < G * D; i += 256) {
            const int g = i >> 7;
            float s = 0.f;
            #pragma unroll
            for (int w = 0; w < NWARP; w++) s += red[w * G * D + i] * wts[w][g];
            g_part_o[(size_t)pbase * D + i] = s;
        }
        if (tid < G) {
            g_part_m[pbase + tid] = m_s[tid];
            g_part_l[pbase + tid] = l_s[tid];
        }
    } else {
        for (int i = tid; i < G * D; i += 256) g_part_o[(size_t)pbase * D + i] = 0.f;
        if (tid < G) { g_part_m[pbase + tid] = NEG; g_part_l[pbase + tid] = 0.f; }
    }

    // ---------- completion count: last CTA of this bh merges the splits ----------
    __threadfence();
    if (tid == 0) {
        int old = atomicAdd(&g_cnt[bh], 1);
        is_last = (old == SPLITS - 1) ? 1 : 0;
    }
    __syncthreads();
    if (!is_last) return;

    for (int i = tid; i < G * D; i += 256) {
        const int g = i >> 7;
        const int d = i & 127;
        float mm = NEG;
        #pragma unroll
        for (int sp = 0; sp < SPLITS; sp++)
            mm = fmaxf(mm, g_part_m[(bh * SPLITS + sp) * G + g]);
        float L = 0.f, o = 0.f;
        #pragma unroll
        for (int sp = 0; sp < SPLITS; sp++) {
            const int   pi = (bh * SPLITS + sp) * G + g;
            const float w  = __expf(g_part_m[pi] - mm);
            L += g_part_l[pi] * w;
            o += g_part_o[(size_t)pi * D + d] * w;
        }
        out[((size_t)b * H + kh * G + g) * D + d] = o / L;
    }
    if (tid == 0) g_cnt[bh] = 0;   // reset for next replay (deterministic)
}

extern "C" void kernel_launch(void* const* d_in, const int* in_sizes, int n_in,
                              void* d_out, int out_size)
{
    const float* q        = (const float*)d_in[0];
    const float* knew     = (const float*)d_in[1];
    const float* vnew     = (const float*)d_in[2];
    const float* kbuf     = (const float*)d_in[3];
    const float* vbuf     = (const float*)d_in[4];
    const int*   req2tok  = (const int*)d_in[5];
    const int*   seq_lens = (const int*)d_in[6];
    const int*   out_loc  = (const int*)d_in[7];
    float*       out      = (float*)d_out;

    dim3 grid(B * HKV, SPLITS);
    attn_fused_kernel<<<grid, 256>>>(q, knew, vnew, kbuf, vbuf,
                                     req2tok, seq_lens, out_loc, out);
}

// round 10
// speedup vs baseline: 1.0020x; 1.0020x over previous
#include <cuda_runtime.h>

#define B 32
#define S 2048
#define H 32
#define HKV 8
#define G 4            // H / HKV
#define D 128
#define SPLITS 4
#define CHUNK (S / SPLITS)   // 512
#define NWARP 8
#define SCALE 0.08838834764831845f
#define NEG -1e30f

// split-KV partial scratch (allocation-free: __device__ globals)
__device__ float g_part_o[B * HKV * SPLITS * G * D];
__device__ float g_part_m[B * HKV * SPLITS * G];
__device__ float g_part_l[B * HKV * SPLITS * G];
__device__ int   g_cnt[B * HKV];   // zero-init; every replay returns it to zero

// 11-shuffle 4-head warp reduction: lane L returns the full 32-lane sum of
// head (L & 3)'s partial. sg[g] holds this lane's partial for head g.
__device__ __forceinline__ float reduce4(float sg[G], int lane)
{
    #pragma unroll
    for (int g = 0; g < G; g++) {
        sg[g] += __shfl_xor_sync(0xffffffffu, sg[g], 1);
        sg[g] += __shfl_xor_sync(0xffffffffu, sg[g], 2);
    }
    const int h = lane & 3;
    float v = (h == 0) ? sg[0] : (h == 1) ? sg[1] : (h == 2) ? sg[2] : sg[3];
    v += __shfl_xor_sync(0xffffffffu, v, 4);
    v += __shfl_xor_sync(0xffffffffu, v, 8);
    v += __shfl_xor_sync(0xffffffffu, v, 16);
    return v;
}

__global__ __launch_bounds__(256, 5) void attn_fused_kernel(
    const float* __restrict__ q,
    const float* __restrict__ knew,
    const float* __restrict__ vnew,
    const float* __restrict__ kbuf,
    const float* __restrict__ vbuf,
    const int*   __restrict__ req_to_token,
    const int*   __restrict__ seq_lens,
    const int*   __restrict__ out_cache_loc,
    float*       __restrict__ out)
{
    const int bh    = blockIdx.x;           // b * HKV + kh
    const int b     = bh / HKV;
    const int kh    = bh % HKV;
    const int split = blockIdx.y;
    const int tid   = threadIdx.x;
    const int lane  = tid & 31;
    const int warp  = tid >> 5;

    const int seq_len = seq_lens[b];
    const int s0      = split * CHUNK;
    const int nt      = min(seq_len - s0, CHUNK);
    const int pbase   = (bh * SPLITS + split) * G;

    // 16 KB shared buffer, time-multiplexed:
    //   phase A (pass 1-3): sc[G][CHUNK] scores->probs (first 8 KB)
    //   phase B (epilogue): red[NWARP][G*D] cross-warp combine (all 16 KB)
    __shared__ float sbuf[NWARP * G * D];
    __shared__ float ml_s[2][G];
    __shared__ int   is_last;
    float (*sc)[CHUNK] = (float (*)[CHUNK])sbuf;

    if (nt > 0) {
        const int out_loc = out_cache_loc[b];

        // q (scaled) in registers: one float4 per head per lane
        float4 qv[G];
        #pragma unroll
        for (int g = 0; g < G; g++) {
            float4 t = *(const float4*)(q + ((size_t)b * H + kh * G + g) * D + lane * 4);
            qv[g] = make_float4(t.x * SCALE, t.y * SCALE, t.z * SCALE, t.w * SCALE);
        }

        const float* knew_ptr = knew + ((size_t)b * HKV + kh) * D;
        const float* vnew_ptr = vnew + ((size_t)b * HKV + kh) * D;
        const int*   rtab     = req_to_token + (size_t)b * S + s0;

        // ---------- Pass 1: QK^T (warp-per-token, 3-deep LDG pipeline) ----------
        {
            int t = warp;
            float4 k0, k1;
            if (t < nt) {                               // prime 2 loads
                const int loc = rtab[t];
                const float* kp = (loc == out_loc) ? knew_ptr
                                                   : (kbuf + ((size_t)loc * HKV + kh) * D);
                k0 = *(const float4*)(kp + lane * 4);
            }
            if (t + NWARP < nt) {
                const int loc = rtab[t + NWARP];
                const float* kp = (loc == out_loc) ? knew_ptr
                                                   : (kbuf + ((size_t)loc * HKV + kh) * D);
                k1 = *(const float4*)(kp + lane * 4);
            }
            for (; t < nt; t += NWARP) {
                const float4 kc = k0;
                k0 = k1;
                const int tn = t + 2 * NWARP;
                if (tn < nt) {                          // refill: keep 2 loads pending
                    const int loc = rtab[tn];
                    const float* kp = (loc == out_loc) ? knew_ptr
                                                       : (kbuf + ((size_t)loc * HKV + kh) * D);
                    k1 = *(const float4*)(kp + lane * 4);
                }
                float sg[G];
                #pragma unroll
                for (int g = 0; g < G; g++)
                    sg[g] = kc.x * qv[g].x + kc.y * qv[g].y + kc.z * qv[g].z + kc.w * qv[g].w;
                float v = reduce4(sg, lane);
                if (lane < 4) sc[lane][t] = v;
            }
        }
        __syncthreads();

        // ---------- Pass 2: per-head max & sum-exp (warps 0..3, head = warp) ----------
        if (warp < G) {
            const int g = warp;
            float m = NEG;
            for (int t = lane; t < nt; t += 32) m = fmaxf(m, sc[g][t]);
            #pragma unroll
            for (int off = 16; off > 0; off >>= 1)
                m = fmaxf(m, __shfl_xor_sync(0xffffffffu, m, off));
            float l = 0.f;
            for (int t = lane; t < nt; t += 32) {
                float e = __expf(sc[g][t] - m);
                sc[g][t] = e;
                l += e;
            }
            #pragma unroll
            for (int off = 16; off > 0; off >>= 1)
                l += __shfl_xor_sync(0xffffffffu, l, off);
            if (lane == 0) { ml_s[0][g] = m; ml_s[1][g] = l; }
        }
        __syncthreads();

        // ---------- Pass 3: P @ V (warp-per-token, 3-deep LDG pipeline) ----------
        float4 acc[G];
        #pragma unroll
        for (int g = 0; g < G; g++) acc[g] = make_float4(0.f, 0.f, 0.f, 0.f);

        {
            int t = warp;
            float4 v0, v1;
            if (t < nt) {                               // prime 2 loads
                const int loc = rtab[t];
                const float* vp = (loc == out_loc) ? vnew_ptr
                                                   : (vbuf + ((size_t)loc * HKV + kh) * D);
                v0 = *(const float4*)(vp + lane * 4);
            }
            if (t + NWARP < nt) {
                const int loc = rtab[t + NWARP];
                const float* vp = (loc == out_loc) ? vnew_ptr
                                                   : (vbuf + ((size_t)loc * HKV + kh) * D);
                v1 = *(const float4*)(vp + lane * 4);
            }
            for (; t < nt; t += NWARP) {
                const float4 vc = v0;
                v0 = v1;
                const int tn = t + 2 * NWARP;
                if (tn < nt) {                          // refill: keep 2 loads pending
                    const int loc = rtab[tn];
                    const float* vp = (loc == out_loc) ? vnew_ptr
                                                       : (vbuf + ((size_t)loc * HKV + kh) * D);
                    v1 = *(const float4*)(vp + lane * 4);
                }
                #pragma unroll
                for (int g = 0; g < G; g++) {
                    const float p = sc[g][t];      // smem broadcast
                    acc[g].x += p * vc.x; acc[g].y += p * vc.y;
                    acc[g].z += p * vc.z; acc[g].w += p * vc.w;
                }
            }
        }
        __syncthreads();                 // all sc reads done: sbuf can be reused
        // deterministic cross-warp reduction via smem (red aliases sc region)
        float* red = sbuf;               // red[NWARP][G*D]
        #pragma unroll
        for (int g = 0; g < G; g++)
            *(float4*)&red[(warp * G + g) * D + lane * 4] = acc[g];
        __syncthreads();

        for (int i = tid; i < G * D; i += 256) {
            float s = red[i];
            #pragma unroll
            for (int w = 1; w < NWARP; w++) s += red[w * G * D + i];
            g_part_o[(size_t)pbase * D + i] = s;
        }
        if (tid < G) {
            g_part_m[pbase + tid] = ml_s[0][tid];
            g_part_l[pbase + tid] = ml_s[1][tid];
        }
    } else {
        for (int i = tid; i < G * D; i += 256) g_part_o[(size_t)pbase * D + i] = 0.f;
        if (tid < G) { g_part_m[pbase + tid] = NEG; g_part_l[pbase + tid] = 0.f; }
    }

    // ---------- completion count: last CTA of this bh merges the splits ----------
    __threadfence();
    if (tid == 0) {
        int old = atomicAdd(&g_cnt[bh], 1);
        is_last = (old == SPLITS - 1) ? 1 : 0;
    }
    __syncthreads();
    if (!is_last) return;

    for (int i = tid; i < G * D; i += 256) {
        const int g = i >> 7;
        const int d = i & 127;
        float m = NEG;
        #pragma unroll
        for (int sp = 0; sp < SPLITS; sp++)
            m = fmaxf(m, g_part_m[(bh * SPLITS + sp) * G + g]);
        float L = 0.f, o = 0.f;
        #pragma unroll
        for (int sp = 0; sp < SPLITS; sp++) {
            const int   pi = (bh * SPLITS + sp) * G + g;
            const float w  = __expf(g_part_m[pi] - m);
            L += g_part_l[pi] * w;
            o += g_part_o[(size_t)pi * D + d] * w;
        }
        out[((size_t)b * H + kh * G + g) * D + d] = o / L;
    }
    if (tid == 0) g_cnt[bh] = 0;   // reset for next replay (deterministic)
}

extern "C" void kernel_launch(void* const* d_in, const int* in_sizes, int n_in,
                              void* d_out, int out_size)
{
    const float* q        = (const float*)d_in[0];
    const float* knew     = (const float*)d_in[1];
    const float* vnew     = (const float*)d_in[2];
    const float* kbuf     = (const float*)d_in[3];
    const float* vbuf     = (const float*)d_in[4];
    const int*   req2tok  = (const int*)d_in[5];
    const int*   seq_lens = (const int*)d_in[6];
    const int*   out_loc  = (const int*)d_in[7];
    float*       out      = (float*)d_out;

    dim3 grid(B * HKV, SPLITS);
    attn_fused_kernel<<<grid, 256>>>(q, knew, vnew, kbuf, vbuf,
                                     req2tok, seq_lens, out_loc, out);
}

// round 11
// speedup vs baseline: 1.3149x; 1.3123x over previous
#include <cuda_runtime.h>

#define B 32
#define S 2048
#define H 32
#define HKV 8
#define G 4            // H / HKV
#define D 128
#define SPLITS 4
#define CHUNK (S / SPLITS)   // 512
#define NWARP 8
#define SCALE 0.08838834764831845f
#define NEG -1e30f

// split-KV partial scratch (allocation-free: __device__ globals)
__device__ float g_part_o[B * HKV * SPLITS * G * D];
__device__ float g_part_m[B * HKV * SPLITS * G];
__device__ float g_part_l[B * HKV * SPLITS * G];
__device__ int   g_cnt[B * HKV];   // zero-init; every replay returns it to zero

// 11-shuffle 4-head warp reduction: lane L returns the full 32-lane sum of
// head (L & 3)'s partial. sg[g] holds this lane's partial for head g.
__device__ __forceinline__ float reduce4(float sg[G], int lane)
{
    #pragma unroll
    for (int g = 0; g < G; g++) {
        sg[g] += __shfl_xor_sync(0xffffffffu, sg[g], 1);
        sg[g] += __shfl_xor_sync(0xffffffffu, sg[g], 2);
    }
    const int h = lane & 3;
    float v = (h == 0) ? sg[0] : (h == 1) ? sg[1] : (h == 2) ? sg[2] : sg[3];
    v += __shfl_xor_sync(0xffffffffu, v, 4);
    v += __shfl_xor_sync(0xffffffffu, v, 8);
    v += __shfl_xor_sync(0xffffffffu, v, 16);
    return v;
}

// streaming float4 load (evict-first: KV lines are single-use)
__device__ __forceinline__ float4 ldcs4(const float* p)
{
    return __ldcs((const float4*)p);
}

__global__ __launch_bounds__(256, 6) void attn_fused_kernel(
    const float* __restrict__ q,
    const float* __restrict__ knew,
    const float* __restrict__ vnew,
    const float* __restrict__ kbuf,
    const float* __restrict__ vbuf,
    const int*   __restrict__ req_to_token,
    const int*   __restrict__ seq_lens,
    const int*   __restrict__ out_cache_loc,
    float*       __restrict__ out)
{
    const int bh    = blockIdx.x;           // b * HKV + kh
    const int b     = bh / HKV;
    const int kh    = bh % HKV;
    const int split = blockIdx.y;
    const int tid   = threadIdx.x;
    const int lane  = tid & 31;
    const int warp  = tid >> 5;

    const int seq_len = seq_lens[b];
    const int s0      = split * CHUNK;
    const int nt      = min(seq_len - s0, CHUNK);
    const int pbase   = (bh * SPLITS + split) * G;

    // 16 KB shared buffer, time-multiplexed:
    //   phase A (pass 1-3): sc[G][CHUNK] scores->probs (first 8 KB)
    //   phase B (epilogue): red[NWARP][G*D] cross-warp combine (all 16 KB)
    __shared__ float sbuf[NWARP * G * D];
    __shared__ int   sidx[CHUNK];           // staged page-table slice (2 KB)
    __shared__ float ml_s[2][G];
    __shared__ int   is_last;
    float (*sc)[CHUNK] = (float (*)[CHUNK])sbuf;

    if (nt > 0) {
        const int out_loc = out_cache_loc[b];

        // q (scaled) in registers: one float4 per head per lane
        float4 qv[G];
        #pragma unroll
        for (int g = 0; g < G; g++) {
            float4 t = *(const float4*)(q + ((size_t)b * H + kh * G + g) * D + lane * 4);
            qv[g] = make_float4(t.x * SCALE, t.y * SCALE, t.z * SCALE, t.w * SCALE);
        }

        const float* knew_ptr = knew + ((size_t)b * HKV + kh) * D;
        const float* vnew_ptr = vnew + ((size_t)b * HKV + kh) * D;
        const int*   rtab     = req_to_token + (size_t)b * S + s0;

        // stage indices once (coalesced) — removes global idx load from the
        // per-iteration critical chain of every K/V load
        for (int i = tid; i < nt; i += 256) sidx[i] = rtab[i];
        __syncthreads();

        // ---------- Pass 1: QK^T (warp-per-token, 2-deep LDG pipeline) ----------
        {
            int t = warp;
            float4 kn;
            if (t < nt) {
                const int loc = sidx[t];
                const float* kp = (loc == out_loc) ? knew_ptr
                                                   : (kbuf + ((size_t)loc * HKV + kh) * D);
                kn = ldcs4(kp + lane * 4);
            }
            for (; t < nt; t += NWARP) {
                const float4 kc = kn;
                const int tn = t + NWARP;
                if (tn < nt) {                          // issue next LDG before compute
                    const int loc = sidx[tn];
                    const float* kp = (loc == out_loc) ? knew_ptr
                                                       : (kbuf + ((size_t)loc * HKV + kh) * D);
                    kn = ldcs4(kp + lane * 4);
                }
                float sg[G];
                #pragma unroll
                for (int g = 0; g < G; g++)
                    sg[g] = kc.x * qv[g].x + kc.y * qv[g].y + kc.z * qv[g].z + kc.w * qv[g].w;
                float v = reduce4(sg, lane);
                if (lane < 4) sc[lane][t] = v;
            }
        }
        __syncthreads();

        // ---------- Pass 2: per-head max & sum-exp (warps 0..3, head = warp) ----------
        if (warp < G) {
            const int g = warp;
            float m = NEG;
            for (int t = lane; t < nt; t += 32) m = fmaxf(m, sc[g][t]);
            #pragma unroll
            for (int off = 16; off > 0; off >>= 1)
                m = fmaxf(m, __shfl_xor_sync(0xffffffffu, m, off));
            float l = 0.f;
            for (int t = lane; t < nt; t += 32) {
                float e = __expf(sc[g][t] - m);
                sc[g][t] = e;
                l += e;
            }
            #pragma unroll
            for (int off = 16; off > 0; off >>= 1)
                l += __shfl_xor_sync(0xffffffffu, l, off);
            if (lane == 0) { ml_s[0][g] = m; ml_s[1][g] = l; }
        }
        __syncthreads();

        // ---------- Pass 3: P @ V (warp-per-token, 2-deep LDG pipeline) ----------
        float4 acc[G];
        #pragma unroll
        for (int g = 0; g < G; g++) acc[g] = make_float4(0.f, 0.f, 0.f, 0.f);

        {
            int t = warp;
            float4 vn;
            if (t < nt) {
                const int loc = sidx[t];
                const float* vp = (loc == out_loc) ? vnew_ptr
                                                   : (vbuf + ((size_t)loc * HKV + kh) * D);
                vn = ldcs4(vp + lane * 4);
            }
            for (; t < nt; t += NWARP) {
                const float4 vc = vn;
                const int tn = t + NWARP;
                if (tn < nt) {                          // issue next LDG before compute
                    const int loc = sidx[tn];
                    const float* vp = (loc == out_loc) ? vnew_ptr
                                                       : (vbuf + ((size_t)loc * HKV + kh) * D);
                    vn = ldcs4(vp + lane * 4);
                }
                #pragma unroll
                for (int g = 0; g < G; g++) {
                    const float p = sc[g][t];      // smem broadcast
                    acc[g].x += p * vc.x; acc[g].y += p * vc.y;
                    acc[g].z += p * vc.z; acc[g].w += p * vc.w;
                }
            }
        }
        __syncthreads();                 // all sc reads done: sbuf can be reused
        // deterministic cross-warp reduction via smem (red aliases sc region)
        float* red = sbuf;               // red[NWARP][G*D]
        #pragma unroll
        for (int g = 0; g < G; g++)
            *(float4*)&red[(warp * G + g) * D + lane * 4] = acc[g];
        __syncthreads();

        for (int i = tid; i < G * D; i += 256) {
            float s = red[i];
            #pragma unroll
            for (int w = 1; w < NWARP; w++) s += red[w * G * D + i];
            g_part_o[(size_t)pbase * D + i] = s;
        }
        if (tid < G) {
            g_part_m[pbase + tid] = ml_s[0][tid];
            g_part_l[pbase + tid] = ml_s[1][tid];
        }
    } else {
        for (int i = tid; i < G * D; i += 256) g_part_o[(size_t)pbase * D + i] = 0.f;
        if (tid < G) { g_part_m[pbase + tid] = NEG; g_part_l[pbase + tid] = 0.f; }
    }

    // ---------- completion count: last CTA of this bh merges the splits ----------
    __threadfence();
    if (tid == 0) {
        int old = atomicAdd(&g_cnt[bh], 1);
        is_last = (old == SPLITS - 1) ? 1 : 0;
    }
    __syncthreads();
    if (!is_last) return;

    for (int i = tid; i < G * D; i += 256) {
        const int g = i >> 7;
        const int d = i & 127;
        float m = NEG;
        #pragma unroll
        for (int sp = 0; sp < SPLITS; sp++)
            m = fmaxf(m, g_part_m[(bh * SPLITS + sp) * G + g]);
        float L = 0.f, o = 0.f;
        #pragma unroll
        for (int sp = 0; sp < SPLITS; sp++) {
            const int   pi = (bh * SPLITS + sp) * G + g;
            const float w  = __expf(g_part_m[pi] - m);
            L += g_part_l[pi] * w;
            o += g_part_o[(size_t)pi * D + d] * w;
        }
        out[((size_t)b * H + kh * G + g) * D + d] = o / L;
    }
    if (tid == 0) g_cnt[bh] = 0;   // reset for next replay (deterministic)
}

extern "C" void kernel_launch(void* const* d_in, const int* in_sizes, int n_in,
                              void* d_out, int out_size)
{
    const float* q        = (const float*)d_in[0];
    const float* knew     = (const float*)d_in[1];
    const float* vnew     = (const float*)d_in[2];
    const float* kbuf     = (const float*)d_in[3];
    const float* vbuf     = (const float*)d_in[4];
    const int*   req2tok  = (const int*)d_in[5];
    const int*   seq_lens = (const int*)d_in[6];
    const int*   out_loc  = (const int*)d_in[7];
    float*       out      = (float*)d_out;

    dim3 grid(B * HKV, SPLITS);
    attn_fused_kernel<<<grid, 256>>>(q, knew, vnew, kbuf, vbuf,
                                     req2tok, seq_lens, out_loc, out);
}

// round 12
// speedup vs baseline: 1.3952x; 1.0610x over previous
#include <cuda_runtime.h>

#define B 32
#define S 2048
#define H 32
#define HKV 8
#define G 4            // H / HKV
#define D 128
#define SPLITS 4
#define CHUNK (S / SPLITS)   // 512
#define NWARP 8
#define SCALE 0.08838834764831845f
#define NEG -1e30f

// split-KV partial scratch (allocation-free: __device__ globals)
__device__ float g_part_o[B * HKV * SPLITS * G * D];
__device__ float g_part_m[B * HKV * SPLITS * G];
__device__ float g_part_l[B * HKV * SPLITS * G];
__device__ int   g_cnt[B * HKV];   // zero-init; every replay returns it to zero

// prologue: write the new token's K/V into the paged pool (idempotent across
// graph replays: same values written every time, matching reference .at[].set)
__global__ __launch_bounds__(256) void store_kv_kernel(
    const float* __restrict__ knew,
    const float* __restrict__ vnew,
    float*       __restrict__ kbuf,
    float*       __restrict__ vbuf,
    const int*   __restrict__ out_cache_loc)
{
    const int b   = blockIdx.x;
    const int tid = threadIdx.x;
    const size_t dst = (size_t)out_cache_loc[b] * HKV * D;
    const size_t src = (size_t)b * HKV * D;
    // HKV*D = 1024 floats = 256 float4 per buffer
    float4 kv = *(const float4*)(knew + src + tid * 4);
    float4 vv = *(const float4*)(vnew + src + tid * 4);
    *(float4*)(kbuf + dst + tid * 4) = kv;
    *(float4*)(vbuf + dst + tid * 4) = vv;
}

// 11-shuffle 4-head warp reduction: lane L returns the full 32-lane sum of
// head (L & 3)'s partial. sg[g] holds this lane's partial for head g.
__device__ __forceinline__ float reduce4(float sg[G], int lane)
{
    #pragma unroll
    for (int g = 0; g < G; g++) {
        sg[g] += __shfl_xor_sync(0xffffffffu, sg[g], 1);
        sg[g] += __shfl_xor_sync(0xffffffffu, sg[g], 2);
    }
    const int h = lane & 3;
    float v = (h == 0) ? sg[0] : (h == 1) ? sg[1] : (h == 2) ? sg[2] : sg[3];
    v += __shfl_xor_sync(0xffffffffu, v, 4);
    v += __shfl_xor_sync(0xffffffffu, v, 8);
    v += __shfl_xor_sync(0xffffffffu, v, 16);
    return v;
}

__global__ __launch_bounds__(256, 6) void attn_fused_kernel(
    const float* __restrict__ q,
    const float* __restrict__ kbuf,
    const float* __restrict__ vbuf,
    const int*   __restrict__ req_to_token,
    const int*   __restrict__ seq_lens,
    float*       __restrict__ out)
{
    const int bh    = blockIdx.x;           // b * HKV + kh
    const int b     = bh / HKV;
    const int kh    = bh % HKV;
    const int split = blockIdx.y;
    const int tid   = threadIdx.x;
    const int lane  = tid & 31;
    const int warp  = tid >> 5;

    const int seq_len = seq_lens[b];
    const int s0      = split * CHUNK;
    const int nt      = min(seq_len - s0, CHUNK);
    const int pbase   = (bh * SPLITS + split) * G;

    // 16 KB shared buffer, time-multiplexed:
    //   phase A (pass 1-3): sc[G][CHUNK] scores->probs (first 8 KB)
    //   phase B (epilogue): red[NWARP][G*D] cross-warp combine (all 16 KB)
    __shared__ float sbuf[NWARP * G * D];
    __shared__ float ml_s[2][G];
    __shared__ int   is_last;
    float (*sc)[CHUNK] = (float (*)[CHUNK])sbuf;

    if (nt > 0) {
        // q (scaled) in registers: one float4 per head per lane
        float4 qv[G];
        #pragma unroll
        for (int g = 0; g < G; g++) {
            float4 t = *(const float4*)(q + ((size_t)b * H + kh * G + g) * D + lane * 4);
            qv[g] = make_float4(t.x * SCALE, t.y * SCALE, t.z * SCALE, t.w * SCALE);
        }

        const int* rtab = req_to_token + (size_t)b * S + s0;
        const size_t khoff = (size_t)kh * D + lane * 4;

        // ---------- Pass 1: QK^T (warp-per-token, 2-deep LDG pipeline) ----------
        {
            int t = warp;
            float4 kn;
            if (t < nt)
                kn = *(const float4*)(kbuf + (size_t)rtab[t] * (HKV * D) + khoff);
            for (; t < nt; t += NWARP) {
                const float4 kc = kn;
                const int tn = t + NWARP;
                if (tn < nt)                            // issue next LDG before compute
                    kn = *(const float4*)(kbuf + (size_t)rtab[tn] * (HKV * D) + khoff);
                float sg[G];
                #pragma unroll
                for (int g = 0; g < G; g++)
                    sg[g] = kc.x * qv[g].x + kc.y * qv[g].y + kc.z * qv[g].z + kc.w * qv[g].w;
                float v = reduce4(sg, lane);
                if (lane < 4) sc[lane][t] = v;
            }
        }
        __syncthreads();

        // ---------- Pass 2: per-head max & sum-exp (warps 0..3, head = warp) ----------
        if (warp < G) {
            const int g = warp;
            float m = NEG;
            for (int t = lane; t < nt; t += 32) m = fmaxf(m, sc[g][t]);
            #pragma unroll
            for (int off = 16; off > 0; off >>= 1)
                m = fmaxf(m, __shfl_xor_sync(0xffffffffu, m, off));
            float l = 0.f;
            for (int t = lane; t < nt; t += 32) {
                float e = __expf(sc[g][t] - m);
                sc[g][t] = e;
                l += e;
            }
            #pragma unroll
            for (int off = 16; off > 0; off >>= 1)
                l += __shfl_xor_sync(0xffffffffu, l, off);
            if (lane == 0) { ml_s[0][g] = m; ml_s[1][g] = l; }
        }
        __syncthreads();

        // ---------- Pass 3: P @ V (warp-per-token, 2-deep LDG pipeline) ----------
        float4 acc[G];
        #pragma unroll
        for (int g = 0; g < G; g++) acc[g] = make_float4(0.f, 0.f, 0.f, 0.f);

        {
            int t = warp;
            float4 vn;
            if (t < nt)
                vn = *(const float4*)(vbuf + (size_t)rtab[t] * (HKV * D) + khoff);
            for (; t < nt; t += NWARP) {
                const float4 vc = vn;
                const int tn = t + NWARP;
                if (tn < nt)                            // issue next LDG before compute
                    vn = *(const float4*)(vbuf + (size_t)rtab[tn] * (HKV * D) + khoff);
                #pragma unroll
                for (int g = 0; g < G; g++) {
                    const float p = sc[g][t];      // smem broadcast
                    acc[g].x += p * vc.x; acc[g].y += p * vc.y;
                    acc[g].z += p * vc.z; acc[g].w += p * vc.w;
                }
            }
        }
        __syncthreads();                 // all sc reads done: sbuf can be reused
        // deterministic cross-warp reduction via smem (red aliases sc region)
        float* red = sbuf;               // red[NWARP][G*D]
        #pragma unroll
        for (int g = 0; g < G; g++)
            *(float4*)&red[(warp * G + g) * D + lane * 4] = acc[g];
        __syncthreads();

        for (int i = tid; i < G * D; i += 256) {
            float s = red[i];
            #pragma unroll
            for (int w = 1; w < NWARP; w++) s += red[w * G * D + i];
            g_part_o[(size_t)pbase * D + i] = s;
        }
        if (tid < G) {
            g_part_m[pbase + tid] = ml_s[0][tid];
            g_part_l[pbase + tid] = ml_s[1][tid];
        }
    } else {
        for (int i = tid; i < G * D; i += 256) g_part_o[(size_t)pbase * D + i] = 0.f;
        if (tid < G) { g_part_m[pbase + tid] = NEG; g_part_l[pbase + tid] = 0.f; }
    }

    // ---------- completion count: last CTA of this bh merges the splits ----------
    __threadfence();
    if (tid == 0) {
        int old = atomicAdd(&g_cnt[bh], 1);
        is_last = (old == SPLITS - 1) ? 1 : 0;
    }
    __syncthreads();
    if (!is_last) return;

    for (int i = tid; i < G * D; i += 256) {
        const int g = i >> 7;
        const int d = i & 127;
        float m = NEG;
        #pragma unroll
        for (int sp = 0; sp < SPLITS; sp++)
            m = fmaxf(m, g_part_m[(bh * SPLITS + sp) * G + g]);
        float L = 0.f, o = 0.f;
        #pragma unroll
        for (int sp = 0; sp < SPLITS; sp++) {
            const int   pi = (bh * SPLITS + sp) * G + g;
            const float w  = __expf(g_part_m[pi] - m);
            L += g_part_l[pi] * w;
            o += g_part_o[(size_t)pi * D + d] * w;
        }
        out[((size_t)b * H + kh * G + g) * D + d] = o / L;
    }
    if (tid == 0) g_cnt[bh] = 0;   // reset for next replay (deterministic)
}

extern "C" void kernel_launch(void* const* d_in, const int* in_sizes, int n_in,
                              void* d_out, int out_size)
{
    const float* q        = (const float*)d_in[0];
    const float* knew     = (const float*)d_in[1];
    const float* vnew     = (const float*)d_in[2];
    float*       kbuf     = (float*)d_in[3];
    float*       vbuf     = (float*)d_in[4];
    const int*   req2tok  = (const int*)d_in[5];
    const int*   seq_lens = (const int*)d_in[6];
    const int*   out_loc  = (const int*)d_in[7];
    float*       out      = (float*)d_out;

    store_kv_kernel<<<B, 256>>>(knew, vnew, kbuf, vbuf, out_loc);
    dim3 grid(B * HKV, SPLITS);
    attn_fused_kernel<<<grid, 256>>>(q, kbuf, vbuf, req2tok, seq_lens, out);
}